// round 10
// baseline (speedup 1.0000x reference)
#include <cuda_runtime.h>
#include <float.h>

#define N_COLS   32000
#define NV4      8000
#define THREADS  256
#define NWARPS   8
#define SLOTS    15          // per-thread float4 stash slots
#define FLATCAP  3072
#define PHASEA   12          // 12*256*4 = 12288 sampled elements
#define NEWTON   12
#define MAX_ROWS 4096
#define SENT     (-1.0e30f)

__device__ float g_row_loss[MAX_ROWS];
__device__ unsigned g_done = 0;

__device__ __forceinline__ float max4(float4 v) {
    return fmaxf(fmaxf(v.x, v.y), fmaxf(v.z, v.w));
}

__global__ void __launch_bounds__(THREADS)
entmax15_fused(const float* __restrict__ inp, const int* __restrict__ tgt,
               float* __restrict__ out, int rows) {
    extern __shared__ char smemraw[];
    float4* sc4  = (float4*)smemraw;                          // SLOTS*256 float4 = 60 KB
    float*  flat = (float*)(smemraw + SLOTS * THREADS * 16);  // FLATCAP floats = 12 KB
    __shared__ float redf[NWARPS];
    __shared__ float redA[NWARPS], redB[NWARPS], redC[NWARPS];
    __shared__ int   scnt[NWARPS];
    __shared__ int   iflags;
    __shared__ int   s_last;
    __shared__ float sred[THREADS];

    const int row  = blockIdx.x;
    const int tid  = threadIdx.x;
    const int lane = tid & 31;
    const int w    = tid >> 5;
    const float* rp = inp + (size_t)row * N_COLS;
    const float4* g4 = (const float4*)rp;

    float tgl = 0.0f;
    if (tid == 0) {
        iflags = 0;
        int ti = tgt[row];
        ti = (ti < 0) ? 0 : ((ti >= N_COLS) ? N_COLS - 1 : ti);
        tgl = __ldg(rp + ti);
    }

    // ---- Sentinel-init stash (unwritten slots must be harmless) ----
    const float4 sv = make_float4(SENT, SENT, SENT, SENT);
    #pragma unroll
    for (int j = 0; j < SLOTS; ++j) sc4[j * THREADS + tid] = sv;

    // ---- Phase A: block max of first 12288 elements -> safe threshold ----
    float e = -FLT_MAX;
    #pragma unroll
    for (int q = 0; q < PHASEA; ++q)
        e = fmaxf(e, max4(g4[q * THREADS + tid]));
    #pragma unroll
    for (int o = 16; o; o >>= 1) e = fmaxf(e, __shfl_xor_sync(0xffffffffu, e, o));
    if (lane == 0) redf[w] = e;
    __syncthreads();                 // B1: sentinels + redf + iflags visible
    float m0 = redf[0];
    #pragma unroll
    for (int k = 1; k < NWARPS; ++k) m0 = fmaxf(m0, redf[k]);
    __syncthreads();                 // B1b: everyone done reading redf
    const float thr = m0 - 2.0f;     // m0 <= m  =>  keeps every true candidate's float4

    // ---- Single DRAM pass: branch-free float4-value stash ----
    // Unconditional store at slot min(cnt,14); rejected writes overwrite a
    // not-yet-owned slot (harmless: all elems < thr <= m-2). Accepts advance cnt.
    int cnt = 0;
    #pragma unroll 4
    for (int p = 0; p < 31; ++p) {
        float4 v = g4[p * THREADS + tid];
        float gm = max4(v);
        int slot = (cnt < SLOTS - 1) ? cnt : (SLOTS - 1);
        sc4[slot * THREADS + tid] = v;
        cnt += (gm >= thr);
    }
    if (tid < 64) {                  // tail: float4s [7936, 8000)
        float4 v = g4[31 * THREADS + tid];
        float gm = max4(v);
        int slot = (cnt < SLOTS - 1) ? cnt : (SLOTS - 1);
        sc4[slot * THREADS + tid] = v;
        cnt += (gm >= thr);
    }

    // ---- Exact row max FROM THE STASH (max's float4 is always stashed) ----
    float lm = -FLT_MAX;
    #pragma unroll
    for (int j = 0; j < SLOTS; ++j) lm = fmaxf(lm, max4(sc4[j * THREADS + tid]));
    #pragma unroll
    for (int o = 16; o; o >>= 1) lm = fmaxf(lm, __shfl_xor_sync(0xffffffffu, lm, o));
    unsigned ob = __ballot_sync(0xffffffffu, cnt >= SLOTS);   // possible data loss
    if (lane == 0) {
        redf[w] = lm;
        if (ob) atomicOr(&iflags, 1);
    }
    __syncthreads();                 // B2
    float m = redf[0];
    #pragma unroll
    for (int k = 1; k < NWARPS; ++k) m = fmaxf(m, redf[k]);
    int ovf = iflags;

    const float cthr = m - 2.0f;     // exact candidate rule: v >= m-2  <=>  X >= -1
    const float cm   = -0.5f * m;

    // ---- Count true candidates per thread (uniform loop over all slots) ----
    int kc = 0;
    if (!ovf) {
        #pragma unroll
        for (int j = 0; j < SLOTS; ++j) {
            float4 q = sc4[j * THREADS + tid];
            kc += (q.x >= cthr) + (q.y >= cthr) + (q.z >= cthr) + (q.w >= cthr);
        }
    }
    // block exclusive scan of kc
    int ws = kc;
    #pragma unroll
    for (int o = 1; o < 32; o <<= 1) {
        int t = __shfl_up_sync(0xffffffffu, ws, o);
        if (lane >= o) ws += t;
    }
    if (lane == 31) scnt[w] = ws;
    __syncthreads();                 // B3
    int base = 0, total = 0;
    #pragma unroll
    for (int q = 0; q < NWARPS; ++q) {
        int c = scnt[q];
        if (q < w) base += c;
        total += c;
    }
    base += ws - kc;
    ovf |= (total > FLATCAP);

    if (!ovf) {
        int pos = base;
        #pragma unroll
        for (int j = 0; j < SLOTS; ++j) {
            float4 q = sc4[j * THREADS + tid];
            float xs[4] = {q.x, q.y, q.z, q.w};
            #pragma unroll
            for (int c = 0; c < 4; ++c) {
                bool kp = (xs[c] >= cthr);
                if (kp) flat[pos] = fmaf(xs[c], 0.5f, cm);   // X = (v-m)/2
                pos += kp;
            }
        }
    }
    __syncthreads();                 // B4: flat complete

    if (!ovf) {
        // ---- Warp 0: Newton on flat candidates (shfl-only, no barriers) ----
        if (w == 0) {
            float tau = -1.0f;
            for (int it = 0; it < NEWTON; ++it) {
                float s1 = 0.0f, s2 = 0.0f;
                for (int i = lane; i < total; i += 32) {
                    float d = fmaxf(flat[i] - tau, 0.0f);
                    s1 += d; s2 = fmaf(d, d, s2);
                }
                #pragma unroll
                for (int o = 16; o; o >>= 1) {
                    s1 += __shfl_xor_sync(0xffffffffu, s1, o);
                    s2 += __shfl_xor_sync(0xffffffffu, s2, o);
                }
                tau += (s2 - 1.0f) / (2.0f * s1);   // convex f, monotone from below
            }
            float sp = 0.0f, s15 = 0.0f, spx = 0.0f;
            for (int i = lane; i < total; i += 32) {
                float x = flat[i];
                float d = fmaxf(x - tau, 0.0f);
                float p = d * d;
                sp += p; s15 = fmaf(p, d, s15); spx = fmaf(p, x, spx);
            }
            #pragma unroll
            for (int o = 16; o; o >>= 1) {
                sp  += __shfl_xor_sync(0xffffffffu, sp,  o);
                s15 += __shfl_xor_sync(0xffffffffu, s15, o);
                spx += __shfl_xor_sync(0xffffffffu, spx, o);
            }
            if (lane == 0) {
                float omega = (1.0f - s15) * (4.0f / 3.0f);
                g_row_loss[row] = omega + 2.0f * spx + m * sp - tgl;
            }
        }
    } else {
        // ---- Fallback (~1e-5 of rows): exact max + Newton over GMEM row ----
        float fm = -FLT_MAX;
        for (int q = tid; q < NV4; q += THREADS) fm = fmaxf(fm, max4(g4[q]));
        #pragma unroll
        for (int o = 16; o; o >>= 1) fm = fmaxf(fm, __shfl_xor_sync(0xffffffffu, fm, o));
        if (lane == 0) redA[w] = fm;
        __syncthreads();
        float mf = redA[0];
        #pragma unroll
        for (int k = 1; k < NWARPS; ++k) mf = fmaxf(mf, redA[k]);
        __syncthreads();
        const float cmf = -0.5f * mf;

        float tau = -1.0f;
        for (int it = 0; it < 14; ++it) {
            float s1 = 0.0f, s2 = 0.0f;
            for (int q = tid; q < NV4; q += THREADS) {
                float4 v = g4[q];
                float xs[4] = {v.x, v.y, v.z, v.w};
                #pragma unroll
                for (int c = 0; c < 4; ++c) {
                    float d = fmaxf(fmaf(xs[c], 0.5f, cmf) - tau, 0.0f);
                    s1 += d; s2 = fmaf(d, d, s2);
                }
            }
            #pragma unroll
            for (int o = 16; o; o >>= 1) {
                s1 += __shfl_xor_sync(0xffffffffu, s1, o);
                s2 += __shfl_xor_sync(0xffffffffu, s2, o);
            }
            if (lane == 0) { redA[w] = s1; redB[w] = s2; }
            __syncthreads();
            float S1 = 0.0f, S2 = 0.0f;
            #pragma unroll
            for (int k = 0; k < NWARPS; ++k) { S1 += redA[k]; S2 += redB[k]; }
            __syncthreads();
            tau += (S2 - 1.0f) / (2.0f * S1);
        }
        float sp = 0.0f, s15 = 0.0f, spx = 0.0f;
        for (int q = tid; q < NV4; q += THREADS) {
            float4 v = g4[q];
            float xs[4] = {v.x, v.y, v.z, v.w};
            #pragma unroll
            for (int c = 0; c < 4; ++c) {
                float x = fmaf(xs[c], 0.5f, cmf);
                float d = fmaxf(x - tau, 0.0f);
                float p = d * d;
                sp += p; s15 = fmaf(p, d, s15); spx = fmaf(p, x, spx);
            }
        }
        #pragma unroll
        for (int o = 16; o; o >>= 1) {
            sp  += __shfl_xor_sync(0xffffffffu, sp,  o);
            s15 += __shfl_xor_sync(0xffffffffu, s15, o);
            spx += __shfl_xor_sync(0xffffffffu, spx, o);
        }
        if (lane == 0) { redA[w] = sp; redB[w] = s15; redC[w] = spx; }
        __syncthreads();
        if (tid == 0) {
            float SP = 0, S15 = 0, SPX = 0;
            #pragma unroll
            for (int k = 0; k < NWARPS; ++k) { SP += redA[k]; S15 += redB[k]; SPX += redC[k]; }
            float omega = (1.0f - S15) * (4.0f / 3.0f);
            g_row_loss[row] = omega + 2.0f * SPX + mf * SP - tgl;
        }
    }

    // ---- Completion: last block computes the mean (deterministic order) ----
    if (tid == 0) {
        __threadfence();
        unsigned old = atomicAdd(&g_done, 1u);
        s_last = (old == (unsigned)gridDim.x - 1u);
    }
    __syncthreads();
    if (s_last) {
        __threadfence();
        float v = 0.0f;
        for (int i = tid; i < rows; i += THREADS) v += g_row_loss[i];
        sred[tid] = v;
        __syncthreads();
        #pragma unroll
        for (int st = THREADS / 2; st; st >>= 1) {
            if (tid < st) sred[tid] += sred[tid + st];
            __syncthreads();
        }
        if (tid == 0) {
            out[0] = sred[0] / (float)rows;
            g_done = 0;   // reset for next graph replay
        }
    }
}

extern "C" void kernel_launch(void* const* d_in, const int* in_sizes, int n_in,
                              void* d_out, int out_size) {
    const float* inp = (const float*)d_in[0];
    const int*   tgt = (const int*)d_in[1];
    float*       out = (float*)d_out;
    const int rows = in_sizes[1];  // 4096

    const int dyn = SLOTS * THREADS * 16 + FLATCAP * 4;   // 60 KB + 12 KB
    cudaFuncSetAttribute(entmax15_fused, cudaFuncAttributeMaxDynamicSharedMemorySize, dyn);
    entmax15_fused<<<rows, THREADS, dyn>>>(inp, tgt, out, rows);
}

// round 12
// speedup vs baseline: 1.0713x; 1.0713x over previous
#include <cuda_runtime.h>
#include <float.h>

#define N_COLS   32000
#define NV4      8000
#define THREADS  256
#define NWARPS   8
#define CHUNKF4  1024        // float4 per chunk (16 KB)
#define NCHUNK   8           // chunk 7 is partial (float4s 7168..7999)
#define SLOTS    16
#define FLATCAP  1024
#define NEWTON   12
#define MAX_ROWS 4096
#define SENT     (-1.0e30f)

__device__ float g_row_loss[MAX_ROWS];
__device__ unsigned g_done = 0;

__device__ __forceinline__ float max4(float4 v) {
    return fmaxf(fmaxf(v.x, v.y), fmaxf(v.z, v.w));
}

__device__ __forceinline__ void cpasync16(unsigned int saddr, const void* gaddr) {
    asm volatile("cp.async.cg.shared.global [%0], [%1], 16;" :: "r"(saddr), "l"(gaddr) : "memory");
}
__device__ __forceinline__ void cpasync_commit() {
    asm volatile("cp.async.commit_group;" ::: "memory");
}
template <int N>
__device__ __forceinline__ void cpasync_wait() {
    asm volatile("cp.async.wait_group %0;" :: "n"(N) : "memory");
}

// Issue chunk k into buf[k&1]; each thread copies its 4 float4 columns.
// Chunk 7's 4th column exists only for tid < 64 (row tail 7936..7999).
__device__ __forceinline__ void issue_chunk(unsigned int sbase, const float4* g4,
                                            int tid, int k) {
    unsigned int sb = sbase + (unsigned int)(((k & 1) * CHUNKF4 + tid) * 16);
    const float4* gp = g4 + k * CHUNKF4 + tid;
    cpasync16(sb,            gp);
    cpasync16(sb + 256 * 16, gp + 256);
    cpasync16(sb + 512 * 16, gp + 512);
    if (k < 7 || tid < 64) cpasync16(sb + 768 * 16, gp + 768);
    cpasync_commit();
}

__global__ void __launch_bounds__(THREADS)
entmax15_fused(const float* __restrict__ inp, const int* __restrict__ tgt,
               float* __restrict__ out, int rows) {
    extern __shared__ char smemraw[];
    float4* buf   = (float4*)smemraw;                                   // 32 KB
    float*  stash = (float*)(smemraw + 2 * CHUNKF4 * 16);               // 16 KB
    float*  flat  = (float*)(smemraw + 2 * CHUNKF4 * 16 + SLOTS * THREADS * 4); // 4 KB
    __shared__ float redf[NWARPS];
    __shared__ float redA[NWARPS], redB[NWARPS], redC[NWARPS];
    __shared__ int   scnt[NWARPS];
    __shared__ int   iflags;
    __shared__ int   s_last;
    __shared__ float sred[THREADS];

    const int row  = blockIdx.x;
    const int tid  = threadIdx.x;
    const int lane = tid & 31;
    const int w    = tid >> 5;
    const float* rp = inp + (size_t)row * N_COLS;
    const float4* g4 = (const float4*)rp;

    float tgl = 0.0f;
    if (tid == 0) {
        iflags = 0;
        int ti = tgt[row];
        ti = (ti < 0) ? 0 : ((ti >= N_COLS) ? N_COLS - 1 : ti);
        tgl = __ldg(rp + ti);
    }

    // sentinel-init own stash column (same-thread use only; no sync needed)
    #pragma unroll
    for (int j = 0; j < SLOTS; ++j) stash[j * THREADS + tid] = SENT;

    const unsigned int sbase = (unsigned int)__cvta_generic_to_shared(buf);

    issue_chunk(sbase, g4, tid, 0);
    issue_chunk(sbase, g4, tid, 1);

    float lmax = -FLT_MAX;
    int kc = 0;

    #pragma unroll 1
    for (int k = 0; k < NCHUNK; ++k) {
        if (k < NCHUNK - 1) cpasync_wait<1>(); else cpasync_wait<0>();

        // own 4 float4s from SMEM (chunk 7: 4th valid only for tid<64)
        const float4* bb = buf + ((k & 1) * CHUNKF4) + tid;
        float4 a = bb[0], b = bb[256], c = bb[512];
        float4 d;
        if (k < 7 || tid < 64) d = bb[768];
        else                   d = make_float4(SENT, SENT, SENT, SENT);

        // refill this buffer for chunk k+2 (regs hold the data now)
        if (k < NCHUNK - 2) issue_chunk(sbase, g4, tid, k + 2);

        lmax = fmaxf(fmaxf(fmaxf(lmax, max4(a)), max4(b)), fmaxf(max4(c), max4(d)));

        // deterministic running block max -> threshold for THIS chunk
        float wm = lmax;
        #pragma unroll
        for (int o = 16; o; o >>= 1) wm = fmaxf(wm, __shfl_xor_sync(0xffffffffu, wm, o));
        if (lane == 0) redf[w] = wm;
        __syncthreads();
        float bm = redf[0];
        #pragma unroll
        for (int q = 1; q < NWARPS; ++q) bm = fmaxf(bm, redf[q]);
        __syncthreads();                 // protect redf before next chunk's write
        const float thr = bm - 2.0f;     // bm <= m  =>  never rejects a true candidate

        // branch-free wrap-stash of all 16 elements
        float xs[16] = {a.x,a.y,a.z,a.w, b.x,b.y,b.z,b.w, c.x,c.y,c.z,c.w, d.x,d.y,d.z,d.w};
        #pragma unroll
        for (int e = 0; e < 16; ++e) {
            int slot = (kc < SLOTS - 1) ? kc : (SLOTS - 1);
            stash[slot * THREADS + tid] = xs[e];
            kc += (xs[e] >= thr);
        }
    }

    // ---- exact row max + overflow flag ----
    float wm = lmax;
    #pragma unroll
    for (int o = 16; o; o >>= 1) wm = fmaxf(wm, __shfl_xor_sync(0xffffffffu, wm, o));
    unsigned ob = __ballot_sync(0xffffffffu, kc >= SLOTS);   // possible stash loss
    if (lane == 0) {
        redf[w] = wm;
        if (ob) atomicOr(&iflags, 1);
    }
    __syncthreads();
    float m = redf[0];
    #pragma unroll
    for (int q = 1; q < NWARPS; ++q) m = fmaxf(m, redf[q]);
    int ovf = iflags;

    const float cthr = m - 2.0f;
    const float cm   = -0.5f * m;

    // ---- count true candidates in stash ----
    int kc2 = 0;
    if (!ovf) {
        #pragma unroll
        for (int j = 0; j < SLOTS; ++j)
            kc2 += (stash[j * THREADS + tid] >= cthr);
    }
    int ws = kc2;
    #pragma unroll
    for (int o = 1; o < 32; o <<= 1) {
        int t = __shfl_up_sync(0xffffffffu, ws, o);
        if (lane >= o) ws += t;
    }
    if (lane == 31) scnt[w] = ws;
    __syncthreads();
    int base = 0, total = 0;
    #pragma unroll
    for (int q = 0; q < NWARPS; ++q) {
        int c = scnt[q];
        if (q < w) base += c;
        total += c;
    }
    base += ws - kc2;
    ovf |= (total > FLATCAP);

    if (!ovf) {
        int pos = base;
        #pragma unroll
        for (int j = 0; j < SLOTS; ++j) {
            float v = stash[j * THREADS + tid];
            bool kp = (v >= cthr);
            if (kp) flat[pos] = fmaf(v, 0.5f, cm);   // X = (v-m)/2
            pos += kp;
        }
    }
    __syncthreads();

    if (!ovf) {
        if (w == 0) {   // warp 0: Newton, shfl-only
            float tau = -1.0f;
            for (int it = 0; it < NEWTON; ++it) {
                float s1 = 0.0f, s2 = 0.0f;
                for (int i = lane; i < total; i += 32) {
                    float d = fmaxf(flat[i] - tau, 0.0f);
                    s1 += d; s2 = fmaf(d, d, s2);
                }
                #pragma unroll
                for (int o = 16; o; o >>= 1) {
                    s1 += __shfl_xor_sync(0xffffffffu, s1, o);
                    s2 += __shfl_xor_sync(0xffffffffu, s2, o);
                }
                tau += (s2 - 1.0f) / (2.0f * s1);   // convex f, monotone from below
            }
            float sp = 0.0f, s15 = 0.0f, spx = 0.0f;
            for (int i = lane; i < total; i += 32) {
                float x = flat[i];
                float d = fmaxf(x - tau, 0.0f);
                float p = d * d;
                sp += p; s15 = fmaf(p, d, s15); spx = fmaf(p, x, spx);
            }
            #pragma unroll
            for (int o = 16; o; o >>= 1) {
                sp  += __shfl_xor_sync(0xffffffffu, sp,  o);
                s15 += __shfl_xor_sync(0xffffffffu, s15, o);
                spx += __shfl_xor_sync(0xffffffffu, spx, o);
            }
            if (lane == 0) {
                float omega = (1.0f - s15) * (4.0f / 3.0f);
                g_row_loss[row] = omega + 2.0f * spx + m * sp - tgl;
            }
        }
    } else {
        // ---- Fallback (vanishing probability): exact max + Newton over GMEM ----
        float fm = -FLT_MAX;
        for (int q = tid; q < NV4; q += THREADS) fm = fmaxf(fm, max4(g4[q]));
        #pragma unroll
        for (int o = 16; o; o >>= 1) fm = fmaxf(fm, __shfl_xor_sync(0xffffffffu, fm, o));
        if (lane == 0) redA[w] = fm;
        __syncthreads();
        float mf = redA[0];
        #pragma unroll
        for (int q = 1; q < NWARPS; ++q) mf = fmaxf(mf, redA[q]);
        __syncthreads();
        const float cmf = -0.5f * mf;

        float tau = -1.0f;
        for (int it = 0; it < 14; ++it) {
            float s1 = 0.0f, s2 = 0.0f;
            for (int q = tid; q < NV4; q += THREADS) {
                float4 v = g4[q];
                float x4[4] = {v.x, v.y, v.z, v.w};
                #pragma unroll
                for (int c = 0; c < 4; ++c) {
                    float d = fmaxf(fmaf(x4[c], 0.5f, cmf) - tau, 0.0f);
                    s1 += d; s2 = fmaf(d, d, s2);
                }
            }
            #pragma unroll
            for (int o = 16; o; o >>= 1) {
                s1 += __shfl_xor_sync(0xffffffffu, s1, o);
                s2 += __shfl_xor_sync(0xffffffffu, s2, o);
            }
            if (lane == 0) { redA[w] = s1; redB[w] = s2; }
            __syncthreads();
            float S1 = 0.0f, S2 = 0.0f;
            #pragma unroll
            for (int q = 0; q < NWARPS; ++q) { S1 += redA[q]; S2 += redB[q]; }
            __syncthreads();
            tau += (S2 - 1.0f) / (2.0f * S1);
        }
        float sp = 0.0f, s15 = 0.0f, spx = 0.0f;
        for (int q = tid; q < NV4; q += THREADS) {
            float4 v = g4[q];
            float x4[4] = {v.x, v.y, v.z, v.w};
            #pragma unroll
            for (int c = 0; c < 4; ++c) {
                float x = fmaf(x4[c], 0.5f, cmf);
                float d = fmaxf(x - tau, 0.0f);
                float p = d * d;
                sp += p; s15 = fmaf(p, d, s15); spx = fmaf(p, x, spx);
            }
        }
        #pragma unroll
        for (int o = 16; o; o >>= 1) {
            sp  += __shfl_xor_sync(0xffffffffu, sp,  o);
            s15 += __shfl_xor_sync(0xffffffffu, s15, o);
            spx += __shfl_xor_sync(0xffffffffu, spx, o);
        }
        if (lane == 0) { redA[w] = sp; redB[w] = s15; redC[w] = spx; }
        __syncthreads();
        if (tid == 0) {
            float SP = 0, S15 = 0, SPX = 0;
            #pragma unroll
            for (int q = 0; q < NWARPS; ++q) { SP += redA[q]; S15 += redB[q]; SPX += redC[q]; }
            float omega = (1.0f - S15) * (4.0f / 3.0f);
            g_row_loss[row] = omega + 2.0f * SPX + mf * SP - tgl;
        }
    }

    // ---- Completion: last block computes the mean (deterministic order) ----
    if (tid == 0) {
        __threadfence();
        unsigned old = atomicAdd(&g_done, 1u);
        s_last = (old == (unsigned)gridDim.x - 1u);
    }
    __syncthreads();
    if (s_last) {
        __threadfence();
        float v = 0.0f;
        for (int i = tid; i < rows; i += THREADS) v += g_row_loss[i];
        sred[tid] = v;
        __syncthreads();
        #pragma unroll
        for (int st = THREADS / 2; st; st >>= 1) {
            if (tid < st) sred[tid] += sred[tid + st];
            __syncthreads();
        }
        if (tid == 0) {
            out[0] = sred[0] / (float)rows;
            g_done = 0;   // reset for next graph replay
        }
    }
}

extern "C" void kernel_launch(void* const* d_in, const int* in_sizes, int n_in,
                              void* d_out, int out_size) {
    const float* inp = (const float*)d_in[0];
    const int*   tgt = (const int*)d_in[1];
    float*       out = (float*)d_out;
    const int rows = in_sizes[1];  // 4096

    const int dyn = 2 * CHUNKF4 * 16 + SLOTS * THREADS * 4 + FLATCAP * 4;  // 52 KB
    cudaFuncSetAttribute(entmax15_fused, cudaFuncAttributeMaxDynamicSharedMemorySize, dyn);
    entmax15_fused<<<rows, THREADS, dyn>>>(inp, tgt, out, rows);
}

// round 13
// speedup vs baseline: 1.3745x; 1.2831x over previous
#include <cuda_runtime.h>
#include <float.h>

#define N_COLS   32000
#define NV4      8000
#define THREADS  256
#define NWARPS   8
#define CHUNKF4  1024        // float4 per chunk (16 KB)
#define NCHUNK   8           // chunk 7 partial: f4 7168..7999
#define SEGW     512         // per-warp provisional-candidate capacity
#define NEWTON   12
#define MAX_ROWS 4096
#define SENT     (-1.0e30f)

__device__ float g_row_loss[MAX_ROWS];
__device__ unsigned g_done = 0;

__device__ __forceinline__ float max4(float4 v) {
    return fmaxf(fmaxf(v.x, v.y), fmaxf(v.z, v.w));
}
__device__ __forceinline__ void cpasync16(unsigned int saddr, const void* gaddr) {
    asm volatile("cp.async.cg.shared.global [%0], [%1], 16;" :: "r"(saddr), "l"(gaddr) : "memory");
}
__device__ __forceinline__ void cpasync_commit() {
    asm volatile("cp.async.commit_group;" ::: "memory");
}
template <int N>
__device__ __forceinline__ void cpasync_wait() {
    asm volatile("cp.async.wait_group %0;" :: "n"(N) : "memory");
}

// Issue chunk k into buf[k&1]; each thread copies its own 4 float4 columns.
// Thread t only ever overwrites smem words t itself consumes -> no sync needed.
__device__ __forceinline__ void issue_chunk(unsigned int sbase, const float4* g4,
                                            int tid, int k) {
    unsigned int sb = sbase + (unsigned int)(((k & 1) * CHUNKF4 + tid) * 16);
    const float4* gp = g4 + k * CHUNKF4 + tid;
    cpasync16(sb,            gp);
    cpasync16(sb + 256 * 16, gp + 256);
    cpasync16(sb + 512 * 16, gp + 512);
    if (k < 7 || tid < 64) cpasync16(sb + 768 * 16, gp + 768);
    cpasync_commit();
}

// Ballot-compacted append of xs[16] elements >= thr into this warp's segment.
// Deterministic order (element slot, then lane). wcnt is warp-uniform.
__device__ __forceinline__ void extract16(const float* xs, float thr,
                                          float* segw, int lane, int& wcnt) {
    const unsigned lm = (1u << lane) - 1u;
    #pragma unroll
    for (int e = 0; e < 16; ++e) {
        bool p = (xs[e] >= thr);
        unsigned b = __ballot_sync(0xffffffffu, p);
        if (p) {
            int pos = wcnt + __popc(b & lm);
            if (pos < SEGW) segw[pos] = xs[e];
        }
        wcnt += __popc(b);
    }
}

__global__ void __launch_bounds__(THREADS)
entmax15_fused(const float* __restrict__ inp, const int* __restrict__ tgt,
               float* __restrict__ out, int rows) {
    extern __shared__ char smemraw[];
    float4* buf = (float4*)smemraw;                        // 32 KB
    float*  seg = (float*)(smemraw + 2 * CHUNKF4 * 16);    // 8*512*4 = 16 KB
    __shared__ float redA[NWARPS], redB[NWARPS], redC[NWARPS];
    __shared__ int   scnt[NWARPS];
    __shared__ int   s_last;
    __shared__ float sred[THREADS];

    const int row  = blockIdx.x;
    const int tid  = threadIdx.x;
    const int lane = tid & 31;
    const int w    = tid >> 5;
    const float* rp = inp + (size_t)row * N_COLS;
    const float4* g4 = (const float4*)rp;
    float* segw = seg + w * SEGW;

    float tgl = 0.0f;
    if (tid == 0) {
        int ti = tgt[row];
        ti = (ti < 0) ? 0 : ((ti >= N_COLS) ? N_COLS - 1 : ti);
        tgl = __ldg(rp + ti);
    }

    const unsigned int sbase = (unsigned int)__cvta_generic_to_shared(buf);
    issue_chunk(sbase, g4, tid, 0);
    issue_chunk(sbase, g4, tid, 1);

    float lmax = -FLT_MAX;
    int wcnt = 0;
    float xs[16];
    float thr;

    // ---- Chunk 0: block-wide threshold (tight: max of 4096 elems) ----
    {
        cpasync_wait<1>();
        const float4* bb = buf + tid;
        float4 a = bb[0], b = bb[256], c = bb[512], d = bb[768];
        issue_chunk(sbase, g4, tid, 2);

        xs[0]=a.x; xs[1]=a.y; xs[2]=a.z; xs[3]=a.w;
        xs[4]=b.x; xs[5]=b.y; xs[6]=b.z; xs[7]=b.w;
        xs[8]=c.x; xs[9]=c.y; xs[10]=c.z; xs[11]=c.w;
        xs[12]=d.x; xs[13]=d.y; xs[14]=d.z; xs[15]=d.w;
        lmax = fmaxf(fmaxf(max4(a), max4(b)), fmaxf(max4(c), max4(d)));

        float wm = lmax;
        #pragma unroll
        for (int o = 16; o; o >>= 1) wm = fmaxf(wm, __shfl_xor_sync(0xffffffffu, wm, o));
        if (lane == 0) redA[w] = wm;
        __syncthreads();
        float m0 = redA[0];
        #pragma unroll
        for (int q = 1; q < NWARPS; ++q) m0 = fmaxf(m0, redA[q]);
        __syncthreads();
        thr = m0 - 2.0f;     // m0 <= m  =>  never rejects a true candidate

        extract16(xs, thr, segw, lane, wcnt);
    }

    // ---- Chunks 1..7: barrier-free; warp-local running threshold ----
    #pragma unroll 1
    for (int k = 1; k < NCHUNK; ++k) {
        if (k < NCHUNK - 1) cpasync_wait<1>(); else cpasync_wait<0>();

        const float4* bb = buf + ((k & 1) * CHUNKF4) + tid;
        float4 a = bb[0], b = bb[256], c = bb[512], d = bb[768];
        if (k == 7 && tid >= 64) d = make_float4(SENT, SENT, SENT, SENT);

        if (k < NCHUNK - 2) issue_chunk(sbase, g4, tid, k + 2);

        xs[0]=a.x; xs[1]=a.y; xs[2]=a.z; xs[3]=a.w;
        xs[4]=b.x; xs[5]=b.y; xs[6]=b.z; xs[7]=b.w;
        xs[8]=c.x; xs[9]=c.y; xs[10]=c.z; xs[11]=c.w;
        xs[12]=d.x; xs[13]=d.y; xs[14]=d.z; xs[15]=d.w;
        lmax = fmaxf(lmax, fmaxf(fmaxf(max4(a), max4(b)), fmaxf(max4(c), max4(d))));

        float wm = lmax;   // warp running max (still a lower bound of m -> safe)
        #pragma unroll
        for (int o = 16; o; o >>= 1) wm = fmaxf(wm, __shfl_xor_sync(0xffffffffu, wm, o));
        thr = fmaxf(thr, wm - 2.0f);

        extract16(xs, thr, segw, lane, wcnt);
    }

    // ---- Exact block max + segment counts ----
    float wm = lmax;
    #pragma unroll
    for (int o = 16; o; o >>= 1) wm = fmaxf(wm, __shfl_xor_sync(0xffffffffu, wm, o));
    if (lane == 0) { redA[w] = wm; scnt[w] = wcnt; }
    __syncthreads();
    float m = redA[0];
    int ovf = 0;
    #pragma unroll
    for (int q = 0; q < NWARPS; ++q) {
        m = fmaxf(m, redA[q]);
        ovf |= (scnt[q] > SEGW);
    }
    const float cm = -0.5f * m;

    // convert own segment to X = (v-m)/2 (provisional extras have X < -1 -> inert)
    const int myc = (wcnt < SEGW) ? wcnt : SEGW;
    for (int i = lane; i < myc; i += 32)
        segw[i] = fmaf(segw[i], 0.5f, cm);
    __syncthreads();

    if (!ovf) {
        // ---- Block-wide Newton on segments ----
        float tau = -1.0f;
        for (int it = 0; it < NEWTON; ++it) {
            float s1 = 0.0f, s2 = 0.0f;
            for (int i = lane; i < myc; i += 32) {
                float d = fmaxf(segw[i] - tau, 0.0f);
                s1 += d; s2 = fmaf(d, d, s2);
            }
            #pragma unroll
            for (int o = 16; o; o >>= 1) {
                s1 += __shfl_xor_sync(0xffffffffu, s1, o);
                s2 += __shfl_xor_sync(0xffffffffu, s2, o);
            }
            if (lane == 0) { redA[w] = s1; redB[w] = s2; }
            __syncthreads();
            float S1 = 0.0f, S2 = 0.0f;
            #pragma unroll
            for (int q = 0; q < NWARPS; ++q) { S1 += redA[q]; S2 += redB[q]; }
            __syncthreads();
            tau += (S2 - 1.0f) / (2.0f * S1);   // convex f, monotone from below
        }

        float sp = 0.0f, s15 = 0.0f, spx = 0.0f;
        for (int i = lane; i < myc; i += 32) {
            float x = segw[i];
            float d = fmaxf(x - tau, 0.0f);
            float p = d * d;
            sp += p; s15 = fmaf(p, d, s15); spx = fmaf(p, x, spx);
        }
        #pragma unroll
        for (int o = 16; o; o >>= 1) {
            sp  += __shfl_xor_sync(0xffffffffu, sp,  o);
            s15 += __shfl_xor_sync(0xffffffffu, s15, o);
            spx += __shfl_xor_sync(0xffffffffu, spx, o);
        }
        if (lane == 0) { redA[w] = sp; redB[w] = s15; redC[w] = spx; }
        __syncthreads();
        if (tid == 0) {
            float SP = 0, S15 = 0, SPX = 0;
            #pragma unroll
            for (int q = 0; q < NWARPS; ++q) { SP += redA[q]; S15 += redB[q]; SPX += redC[q]; }
            float omega = (1.0f - S15) * (4.0f / 3.0f);
            g_row_loss[row] = omega + 2.0f * SPX + m * SP - tgl;
        }
    } else {
        // ---- Fallback (vanishing probability): Newton over GMEM row ----
        float tau = -1.0f;
        for (int it = 0; it < 14; ++it) {
            float s1 = 0.0f, s2 = 0.0f;
            for (int q = tid; q < NV4; q += THREADS) {
                float4 v = g4[q];
                float x4[4] = {v.x, v.y, v.z, v.w};
                #pragma unroll
                for (int c = 0; c < 4; ++c) {
                    float d = fmaxf(fmaf(x4[c], 0.5f, cm) - tau, 0.0f);
                    s1 += d; s2 = fmaf(d, d, s2);
                }
            }
            #pragma unroll
            for (int o = 16; o; o >>= 1) {
                s1 += __shfl_xor_sync(0xffffffffu, s1, o);
                s2 += __shfl_xor_sync(0xffffffffu, s2, o);
            }
            if (lane == 0) { redA[w] = s1; redB[w] = s2; }
            __syncthreads();
            float S1 = 0.0f, S2 = 0.0f;
            #pragma unroll
            for (int q = 0; q < NWARPS; ++q) { S1 += redA[q]; S2 += redB[q]; }
            __syncthreads();
            tau += (S2 - 1.0f) / (2.0f * S1);
        }
        float sp = 0.0f, s15 = 0.0f, spx = 0.0f;
        for (int q = tid; q < NV4; q += THREADS) {
            float4 v = g4[q];
            float x4[4] = {v.x, v.y, v.z, v.w};
            #pragma unroll
            for (int c = 0; c < 4; ++c) {
                float x = fmaf(x4[c], 0.5f, cm);
                float d = fmaxf(x - tau, 0.0f);
                float p = d * d;
                sp += p; s15 = fmaf(p, d, s15); spx = fmaf(p, x, spx);
            }
        }
        #pragma unroll
        for (int o = 16; o; o >>= 1) {
            sp  += __shfl_xor_sync(0xffffffffu, sp,  o);
            s15 += __shfl_xor_sync(0xffffffffu, s15, o);
            spx += __shfl_xor_sync(0xffffffffu, spx, o);
        }
        if (lane == 0) { redA[w] = sp; redB[w] = s15; redC[w] = spx; }
        __syncthreads();
        if (tid == 0) {
            float SP = 0, S15 = 0, SPX = 0;
            #pragma unroll
            for (int q = 0; q < NWARPS; ++q) { SP += redA[q]; S15 += redB[q]; SPX += redC[q]; }
            float omega = (1.0f - S15) * (4.0f / 3.0f);
            g_row_loss[row] = omega + 2.0f * SPX + m * SP - tgl;
        }
    }

    // ---- Completion: last block computes the mean (deterministic order) ----
    if (tid == 0) {
        __threadfence();
        unsigned old = atomicAdd(&g_done, 1u);
        s_last = (old == (unsigned)gridDim.x - 1u);
    }
    __syncthreads();
    if (s_last) {
        __threadfence();
        float v = 0.0f;
        for (int i = tid; i < rows; i += THREADS) v += g_row_loss[i];
        sred[tid] = v;
        __syncthreads();
        #pragma unroll
        for (int st = THREADS / 2; st; st >>= 1) {
            if (tid < st) sred[tid] += sred[tid + st];
            __syncthreads();
        }
        if (tid == 0) {
            out[0] = sred[0] / (float)rows;
            g_done = 0;   // reset for next graph replay
        }
    }
}

extern "C" void kernel_launch(void* const* d_in, const int* in_sizes, int n_in,
                              void* d_out, int out_size) {
    const float* inp = (const float*)d_in[0];
    const int*   tgt = (const int*)d_in[1];
    float*       out = (float*)d_out;
    const int rows = in_sizes[1];  // 4096

    const int dyn = 2 * CHUNKF4 * 16 + NWARPS * SEGW * 4;   // 48 KB
    cudaFuncSetAttribute(entmax15_fused, cudaFuncAttributeMaxDynamicSharedMemorySize, dyn);
    entmax15_fused<<<rows, THREADS, dyn>>>(inp, tgt, out, rows);
}